// round 16
// baseline (speedup 1.0000x reference)
#include <cuda_runtime.h>
#include <cuda_fp16.h>
#include <math.h>
#include <stdint.h>

#define T_TOK 8192
#define D_DIM 1024
#define F_DIM 4096
#define E_NUM 8
#define A_TOT (2 * T_TOK)      /* 16384 real (token, expert) assignments */
#define A_PAD 18432            /* A_TOT + 8*256 padding, multiple of 256 */
#define NMT   (A_PAD / 128)    /* 144 global 128-row M-slabs */
#define NCH1  (D_DIM / 16)     /* 64 K16-chunks, GEMM1 */
#define NCH2  (F_DIM / 16)     /* 256 K16-chunks, GEMM2 */
#define NT1   (F_DIM / 128)    /* 32 N-tiles, GEMM1 */
#define NT2   (D_DIM / 128)    /* 8 N-tiles, GEMM2 */

// ---------------- scratch (no allocation allowed -> device globals) --------
__device__ int   g_counts[E_NUM];
__device__ int   g_offsets[E_NUM + 1];          // PADDED offsets (mult of 256)
__device__ int   g_expidx[A_TOT];
__device__ int   g_pos[A_TOT];
__device__ float g_wt[A_TOT];
__device__ int   g_slot[A_TOT];
__device__ int   g_sorted_tok[A_PAD];
__device__ float g_sorted_wt[A_PAD];
// fp16 fragment slabs: one (128-row tile, chunk) slab = 2048 halves = 256 uint4
__device__ __half g_xa[(size_t)NMT * NCH1 * 2048];           //  38 MB A-frags GEMM1
__device__ __half g_hf[(size_t)NMT * NCH2 * 2048];           // 151 MB A-frags GEMM2
__device__ __half g_w1f[(size_t)E_NUM * NT1 * NCH1 * 2048];  //  64 MB B-frags GEMM1
__device__ __half g_w2f[(size_t)E_NUM * NT2 * NCH2 * 2048];  //  64 MB B-frags GEMM2
__device__ float  g_y[(size_t)A_PAD * D_DIM];                //  75 MB per-assignment outputs

__device__ __forceinline__ float gelu_exact(float v) {
    return 0.5f * v * (1.0f + erff(v * 0.70710678118654752440f));
}

__device__ __forceinline__ uint32_t h2u(__half2 h) {
    return *(uint32_t*)&h;
}

// m16n8k16 fp16 mma, fp32 accumulate: C[16x8] += A[16x16] * B[16x8]
__device__ __forceinline__ void mma_f16(float* c, const uint32_t* a,
                                        uint32_t b0, uint32_t b1) {
    asm volatile(
        "mma.sync.aligned.m16n8k16.row.col.f32.f16.f16.f32 "
        "{%0,%1,%2,%3}, {%4,%5,%6,%7}, {%8,%9}, {%0,%1,%2,%3};"
        : "+f"(c[0]), "+f"(c[1]), "+f"(c[2]), "+f"(c[3])
        : "r"(a[0]), "r"(a[1]), "r"(a[2]), "r"(a[3]), "r"(b0), "r"(b1));
}

// ---------------------------------------------------------------------------
__global__ void zero_kernel() {
    if (threadIdx.x < E_NUM) g_counts[threadIdx.x] = 0;
}

// Gate v3: 8 tokens per 256-thread block (warp per token); gw transposed into
// smem once per block; x via coalesced LDG.128; gwT via conflict-free LDS.128.
__global__ __launch_bounds__(256) void gate_kernel(const float* __restrict__ x,
                                                   const float* __restrict__ gw) {
    __shared__ float gwT[8][1032];   // [e][j], padded row
    const int tid = threadIdx.x;
#pragma unroll
    for (int p = 0; p < 8; p++) {
        int q = tid + p * 256;              // float4 index into gw (2048 total)
        float4 v = ((const float4*)gw)[q];
        int j = q >> 1;
        int e0 = (q & 1) * 4;
        gwT[e0 + 0][j] = v.x;
        gwT[e0 + 1][j] = v.y;
        gwT[e0 + 2][j] = v.z;
        gwT[e0 + 3][j] = v.w;
    }
    __syncthreads();

    const int w = tid >> 5, lane = tid & 31;
    const int t = blockIdx.x * 8 + w;
    const float4* xr = (const float4*)(x + (size_t)t * D_DIM);
    float4 xv[8];
#pragma unroll
    for (int i = 0; i < 8; i++) xv[i] = xr[lane + i * 32];

    float acc[8];
#pragma unroll
    for (int e = 0; e < 8; e++) {
        float a = 0.0f;
#pragma unroll
        for (int i = 0; i < 8; i++) {
            const float4 gv = *(const float4*)&gwT[e][(lane + i * 32) * 4];
            a += xv[i].x * gv.x + xv[i].y * gv.y + xv[i].z * gv.z + xv[i].w * gv.w;
        }
        acc[e] = a;
    }
#pragma unroll
    for (int s = 16; s > 0; s >>= 1) {
#pragma unroll
        for (int e = 0; e < 8; e++)
            acc[e] += __shfl_xor_sync(0xffffffffu, acc[e], s);
    }
    if (lane == 0) {
        int i0 = 0;
#pragma unroll
        for (int e = 1; e < 8; e++) if (acc[e] > acc[i0]) i0 = e;
        int i1 = (i0 == 0) ? 1 : 0;
#pragma unroll
        for (int e = 0; e < 8; e++) if (e != i1 && e != i0 && acc[e] > acc[i1]) i1 = e;
        float e1 = expf(acc[i1] - acc[i0]);
        float inv = 1.0f / (1.0f + e1);
        int p0 = atomicAdd(&g_counts[i0], 1);
        int p1 = atomicAdd(&g_counts[i1], 1);
        g_expidx[2 * t + 0] = i0;
        g_expidx[2 * t + 1] = i1;
        g_pos[2 * t + 0] = p0;
        g_pos[2 * t + 1] = p1;
        g_wt[2 * t + 0] = inv;
        g_wt[2 * t + 1] = e1 * inv;
    }
}

__global__ void scan_kernel() {
    if (threadIdx.x == 0) {
        int s = 0;
#pragma unroll
        for (int e = 0; e < E_NUM; e++) {
            g_offsets[e] = s;
            s += (g_counts[e] + 255) & ~255;   // pad each expert to 256
        }
        g_offsets[E_NUM] = s;
    }
}

__global__ void scatter_kernel() {
    int i = blockIdx.x * 256 + threadIdx.x;
    if (i >= A_TOT) return;
    int e = g_expidx[i];
    int s = g_offsets[e] + g_pos[i];
    g_slot[i] = s;
    g_sorted_tok[s] = i >> 1;
    g_sorted_wt[s] = g_wt[i];
}

// Fill padding slots with tok=0, wt=0.
__global__ void pad_fill_kernel() {
    int s = blockIdx.x * 256 + threadIdx.x;
    if (s >= A_PAD) return;
    int e = 0;
#pragma unroll
    for (int i = 1; i < E_NUM; i++) if (s >= g_offsets[i]) e = i;
    int local = s - g_offsets[e];
    if (local >= g_counts[e]) {
        g_sorted_tok[s] = 0;
        g_sorted_wt[s] = 0.0f;
    }
}

// ---------------- fragment pre-format kernels (fp16) ------------------------
// Gather routed x rows into A-fragment slabs.
__global__ __launch_bounds__(256) void xfrag_kernel(const float* __restrict__ x) {
    const int ch = blockIdx.x;
    const int mt = blockIdx.y;
    __shared__ float sx[128 * 20];
    __shared__ int toks[128];
    const int tid = threadIdx.x;
    if (tid < 128) toks[tid] = g_sorted_tok[mt * 128 + tid];
    __syncthreads();
#pragma unroll
    for (int p = 0; p < 2; p++) {
        int q = tid + p * 256;
        int row = q >> 2, kq = q & 3;
        float4 v = *(const float4*)(x + (size_t)toks[row] * D_DIM + ch * 16 + kq * 4);
        *(float4*)&sx[row * 20 + kq * 4] = v;
    }
    __syncthreads();
    const int mb = tid >> 5, lane = tid & 31;
    const int g = lane >> 2, t = lane & 3;
    const int r0 = mb * 16 + g;
    uint4 v;
    v.x = h2u(__floats2half2_rn(sx[r0 * 20 + 2 * t],           sx[r0 * 20 + 2 * t + 1]));
    v.y = h2u(__floats2half2_rn(sx[(r0 + 8) * 20 + 2 * t],     sx[(r0 + 8) * 20 + 2 * t + 1]));
    v.z = h2u(__floats2half2_rn(sx[r0 * 20 + 2 * t + 8],       sx[r0 * 20 + 2 * t + 9]));
    v.w = h2u(__floats2half2_rn(sx[(r0 + 8) * 20 + 2 * t + 8], sx[(r0 + 8) * 20 + 2 * t + 9]));
    uint4* dst = (uint4*)(g_xa + ((size_t)mt * NCH1 + ch) * 2048);
    dst[tid] = v;
}

// Reformat weights [e][K][N] row-major -> fp16 B-fragment slabs.
__global__ __launch_bounds__(256) void wfrag_kernel(const float* __restrict__ w,
                                                    __half* __restrict__ dstbase,
                                                    int Ndim) {
    const int nt = blockIdx.x;
    const int ch = blockIdx.y;
    const int e = blockIdx.z;
    const int Kdim = gridDim.y * 16;
    __shared__ float s[16 * 132];
    const float* src = w + (size_t)e * Kdim * Ndim + (size_t)(ch * 16) * Ndim + nt * 128;
    const int tid = threadIdx.x;
#pragma unroll
    for (int p = 0; p < 2; p++) {
        int q = tid + p * 256;
        int kk = q >> 5, nn = q & 31;
        float4 v = *(const float4*)(src + (size_t)kk * Ndim + nn * 4);
        *(float4*)&s[kk * 132 + nn * 4] = v;
    }
    __syncthreads();
    const int np = tid >> 5, lane = tid & 31;
    const int g = lane >> 2, t = lane & 3;
    const int c0 = np * 16 + g, c1 = c0 + 8;
    uint4 v;
    v.x = h2u(__floats2half2_rn(s[(2 * t) * 132 + c0],     s[(2 * t + 1) * 132 + c0]));
    v.y = h2u(__floats2half2_rn(s[(2 * t + 8) * 132 + c0], s[(2 * t + 9) * 132 + c0]));
    v.z = h2u(__floats2half2_rn(s[(2 * t) * 132 + c1],     s[(2 * t + 1) * 132 + c1]));
    v.w = h2u(__floats2half2_rn(s[(2 * t + 8) * 132 + c1], s[(2 * t + 9) * 132 + c1]));
    uint4* dst = (uint4*)(dstbase + (((size_t)e * gridDim.x + nt) * gridDim.y + ch) * 2048);
    dst[tid] = v;
}

// ---------------- mma.sync fp16 grouped GEMM (smem-free, sw-pipelined) ------
// CTA 256(M) x 128(N), 16 warps as 8(M)x2(N), warp tile 32x64. 512 threads,
// 1 CTA/SM = 16 warps/SM (same warp count/SM as champion, same per-thread code).
// B fragments now shared by 8 warps via L1 (was 4); per-area L2 traffic -33%.
// Per-expert regions padded to 256 rows so both slabs belong to the expert.
template<int NCHUNK, int FFN1>
__global__ __launch_bounds__(512, 1)
void ffn_mma(const __half* __restrict__ Afrag,
             const __half* __restrict__ Bfrag,
             const float* __restrict__ bias,
             float* __restrict__ outf,
             __half* __restrict__ outh,
             int out_n) {
    const int e = blockIdx.z;
    const int cnt = g_counts[e];
    const int m0 = blockIdx.y * 256;
    if (m0 >= cnt) return;
    const int off = g_offsets[e];                   // padded, multiple of 256
    const int mt0 = (off >> 7) + blockIdx.y * 2;    // first 128-slab of this CTA
    const int nt = blockIdx.x;

    const int tid = threadIdx.x;
    const int wid = tid >> 5;
    const int lane = tid & 31;
    const int warp_m = wid >> 1;   // 0..7 (rows warp_m*32 .. +31)
    const int warp_n = wid & 1;    // 0..1
    const int mts = mt0 + (warp_m >> 2);   // this warp's 128-slab
    const int wm = warp_m & 3;             // position within slab

    const uint4* au = (const uint4*)Afrag + (size_t)mts * NCHUNK * 256
                    + wm * 64 + lane;          // 2 A-blocks per warp
    const uint4* bu = (const uint4*)Bfrag + ((size_t)e * gridDim.x + nt) * NCHUNK * 256
                    + warp_n * 128 + lane;     // 4 B-blocks per warp

    float c[2][8][4];
#pragma unroll
    for (int mi = 0; mi < 2; mi++)
#pragma unroll
        for (int ni = 0; ni < 8; ni++)
#pragma unroll
            for (int j = 0; j < 4; j++) c[mi][ni][j] = 0.0f;

    uint4 av[2][2];
    uint4 bv[2][4];
    av[0][0] = au[0];  av[0][1] = au[32];
    bv[0][0] = bu[0];  bv[0][1] = bu[32];
    bv[0][2] = bu[64]; bv[0][3] = bu[96];

#pragma unroll 2
    for (int ch = 0; ch < NCHUNK; ch++) {
        const int cur = ch & 1;
        const int nxt = cur ^ 1;
        if (ch + 1 < NCHUNK) {
            const uint4* ap = au + (size_t)(ch + 1) * 256;
            const uint4* bp = bu + (size_t)(ch + 1) * 256;
            av[nxt][0] = ap[0];  av[nxt][1] = ap[32];
            bv[nxt][0] = bp[0];  bv[nxt][1] = bp[32];
            bv[nxt][2] = bp[64]; bv[nxt][3] = bp[96];
        }
#pragma unroll
        for (int pi = 0; pi < 4; pi++)
#pragma unroll
            for (int mi = 0; mi < 2; mi++) {
                mma_f16(c[mi][2 * pi + 0], (const uint32_t*)&av[cur][mi],
                        bv[cur][pi].x, bv[cur][pi].y);
                mma_f16(c[mi][2 * pi + 1], (const uint32_t*)&av[cur][mi],
                        bv[cur][pi].z, bv[cur][pi].w);
            }
    }

    const int g = lane >> 2;
    const int t = lane & 3;

    if (FFN1) {
        // Write h (fp16) into GEMM2 A-fragment layout, one STG.128 per
        // (mi, ni-pair). No row checks: overflow lands in the expert's
        // 256-row padding (both slabs belong to this expert).
        const int nb = (nt * 128 + warp_n * 64) >> 4;   // base ch2
        const float* bcol = bias + (size_t)e * F_DIM + nt * 128 + warp_n * 64 + t * 2;
#pragma unroll
        for (int mi = 0; mi < 2; mi++) {
            const int mb = wm * 2 + mi;
#pragma unroll
            for (int p = 0; p < 4; p++) {
                float2 b0 = *(const float2*)(bcol + p * 16);
                float2 b1 = *(const float2*)(bcol + p * 16 + 8);
                const int ni0 = 2 * p, ni1 = 2 * p + 1;
                uint4 u;
                u.x = h2u(__floats2half2_rn(gelu_exact(c[mi][ni0][0] + b0.x),
                                            gelu_exact(c[mi][ni0][1] + b0.y)));
                u.y = h2u(__floats2half2_rn(gelu_exact(c[mi][ni0][2] + b0.x),
                                            gelu_exact(c[mi][ni0][3] + b0.y)));
                u.z = h2u(__floats2half2_rn(gelu_exact(c[mi][ni1][0] + b1.x),
                                            gelu_exact(c[mi][ni1][1] + b1.y)));
                u.w = h2u(__floats2half2_rn(gelu_exact(c[mi][ni1][2] + b1.x),
                                            gelu_exact(c[mi][ni1][3] + b1.y)));
                *(uint4*)(outh + (((size_t)mts * NCH2 + nb + p) * 8 + mb) * 256
                          + lane * 8) = u;
            }
        }
    } else {
        const float* brow = bias + (size_t)e * out_n + nt * 128;
#pragma unroll
        for (int mi = 0; mi < 2; mi++) {
#pragma unroll
            for (int rh = 0; rh < 2; rh++) {
                int r = warp_m * 32 + mi * 16 + g + rh * 8;   // 0..255
                size_t srow = (size_t)(off + m0 + r);   // pad rows: wt=0, never read
                float wt = g_sorted_wt[srow];
                float* orow = outf + srow * (size_t)out_n + nt * 128;
#pragma unroll
                for (int ni = 0; ni < 8; ni++) {
                    int col = warp_n * 64 + ni * 8 + t * 2;
                    float2 bb = *(const float2*)(brow + col);
                    float2 o;
                    o.x = wt * (c[mi][ni][rh * 2 + 0] + bb.x);
                    o.y = wt * (c[mi][ni][rh * 2 + 1] + bb.y);
                    *(float2*)(orow + col) = o;
                }
            }
        }
    }
}

// out[t, d] = y[slot0(t), d] + y[slot1(t), d]  (float4-wide)
__global__ __launch_bounds__(256) void combine_kernel(float4* __restrict__ out) {
    int i4 = blockIdx.x * 256 + threadIdx.x;   // float4 index, T*D/4 total
    int t = i4 >> 8;
    int d4 = i4 & 255;
    int s0 = g_slot[2 * t + 0];
    int s1 = g_slot[2 * t + 1];
    float4 a = ((const float4*)(g_y + (size_t)s0 * D_DIM))[d4];
    float4 b = ((const float4*)(g_y + (size_t)s1 * D_DIM))[d4];
    float4 o;
    o.x = a.x + b.x;
    o.y = a.y + b.y;
    o.z = a.z + b.z;
    o.w = a.w + b.w;
    out[i4] = o;
}

// ---------------------------------------------------------------------------
extern "C" void kernel_launch(void* const* d_in, const int* in_sizes, int n_in,
                              void* d_out, int out_size) {
    const float* x  = (const float*)d_in[0];
    const float* gw = (const float*)d_in[1];
    const float* w1 = (const float*)d_in[2];
    const float* b1 = (const float*)d_in[3];
    const float* w2 = (const float*)d_in[4];
    const float* b2 = (const float*)d_in[5];
    float* out = (float*)d_out;

    __half* xa;  cudaGetSymbolAddress((void**)&xa,  g_xa);
    __half* hf;  cudaGetSymbolAddress((void**)&hf,  g_hf);
    __half* w1f; cudaGetSymbolAddress((void**)&w1f, g_w1f);
    __half* w2f; cudaGetSymbolAddress((void**)&w2f, g_w2f);
    float* ybuf; cudaGetSymbolAddress((void**)&ybuf, g_y);

    zero_kernel<<<1, 32>>>();
    gate_kernel<<<T_TOK / 8, 256>>>(x, gw);
    scan_kernel<<<1, 32>>>();
    scatter_kernel<<<A_TOT / 256, 256>>>();
    pad_fill_kernel<<<(A_PAD + 255) / 256, 256>>>();

    // Pre-format: weights + gathered activations into fp16 fragment slabs.
    wfrag_kernel<<<dim3(NT1, NCH1, E_NUM), 256>>>(w1, w1f, F_DIM);
    wfrag_kernel<<<dim3(NT2, NCH2, E_NUM), 256>>>(w2, w2f, D_DIM);
    xfrag_kernel<<<dim3(NCH1, NMT), 256>>>(x);

    // GEMM1: h = gelu(x @ w1 + b1) -> g_hf (fp16 fragment layout)
    ffn_mma<NCH1, 1><<<dim3(NT1, A_TOT / 256, E_NUM), 512>>>(
        xa, w1f, b1, nullptr, hf, F_DIM);
    // GEMM2: y = wt * (h @ w2 + b2) -> g_y (fp32 row-major)
    ffn_mma<NCH2, 0><<<dim3(NT2, A_TOT / 256, E_NUM), 512>>>(
        hf, w2f, b2, ybuf, nullptr, D_DIM);

    combine_kernel<<<(T_TOK * D_DIM / 4) / 256, 256>>>((float4*)out);
}

// round 17
// speedup vs baseline: 1.1203x; 1.1203x over previous
#include <cuda_runtime.h>
#include <cuda_fp16.h>
#include <math.h>
#include <stdint.h>

#define T_TOK 8192
#define D_DIM 1024
#define F_DIM 4096
#define E_NUM 8
#define A_TOT (2 * T_TOK)      /* 16384 real (token, expert) assignments */
#define A_PAD 17408            /* A_TOT + 8*128 padding, multiple of 128 */
#define NMT   (A_PAD / 128)    /* 136 global 128-row M-slabs */
#define NCH1  (D_DIM / 16)     /* 64 K16-chunks, GEMM1 */
#define NCH2  (F_DIM / 16)     /* 256 K16-chunks, GEMM2 */
#define NT1   (F_DIM / 128)    /* 32 N-tiles, GEMM1 */
#define NT2   (D_DIM / 128)    /* 8 N-tiles, GEMM2 */

// ---------------- scratch (no allocation allowed -> device globals) --------
__device__ int   g_counts[E_NUM];
__device__ int   g_offsets[E_NUM + 1];          // PADDED offsets (mult of 128)
__device__ int   g_expidx[A_TOT];
__device__ int   g_pos[A_TOT];
__device__ float g_wt[A_TOT];
__device__ int   g_slot[A_TOT];
__device__ int   g_sorted_tok[A_PAD];
__device__ float g_sorted_wt[A_PAD];
// fp16 fragment slabs: one (tile, chunk) slab = 2048 halves = 4 KB = 256 uint4
__device__ __half g_xa[(size_t)NMT * NCH1 * 2048];           //  34 MB A-frags GEMM1
__device__ __half g_hf[(size_t)NMT * NCH2 * 2048];           // 142 MB A-frags GEMM2
__device__ __half g_w1f[(size_t)E_NUM * NT1 * NCH1 * 2048];  //  64 MB B-frags GEMM1
__device__ __half g_w2f[(size_t)E_NUM * NT2 * NCH2 * 2048];  //  64 MB B-frags GEMM2
__device__ __half g_y[(size_t)A_PAD * D_DIM];                //  36 MB outputs (fp16)

__device__ __forceinline__ float gelu_exact(float v) {
    return 0.5f * v * (1.0f + erff(v * 0.70710678118654752440f));
}

__device__ __forceinline__ uint32_t h2u(__half2 h) {
    return *(uint32_t*)&h;
}

// m16n8k16 fp16 mma, fp32 accumulate: C[16x8] += A[16x16] * B[16x8]
__device__ __forceinline__ void mma_f16(float* c, const uint32_t* a,
                                        uint32_t b0, uint32_t b1) {
    asm volatile(
        "mma.sync.aligned.m16n8k16.row.col.f32.f16.f16.f32 "
        "{%0,%1,%2,%3}, {%4,%5,%6,%7}, {%8,%9}, {%0,%1,%2,%3};"
        : "+f"(c[0]), "+f"(c[1]), "+f"(c[2]), "+f"(c[3])
        : "r"(a[0]), "r"(a[1]), "r"(a[2]), "r"(a[3]), "r"(b0), "r"(b1));
}

// ---------------------------------------------------------------------------
__global__ void zero_kernel() {
    if (threadIdx.x < E_NUM) g_counts[threadIdx.x] = 0;
}

// Gate v3: 8 tokens per 256-thread block (warp per token); gw transposed into
// smem once per block; x via coalesced LDG.128; gwT via conflict-free LDS.128.
__global__ __launch_bounds__(256) void gate_kernel(const float* __restrict__ x,
                                                   const float* __restrict__ gw) {
    __shared__ float gwT[8][1032];   // [e][j], padded row
    const int tid = threadIdx.x;
#pragma unroll
    for (int p = 0; p < 8; p++) {
        int q = tid + p * 256;              // float4 index into gw (2048 total)
        float4 v = ((const float4*)gw)[q];
        int j = q >> 1;
        int e0 = (q & 1) * 4;
        gwT[e0 + 0][j] = v.x;
        gwT[e0 + 1][j] = v.y;
        gwT[e0 + 2][j] = v.z;
        gwT[e0 + 3][j] = v.w;
    }
    __syncthreads();

    const int w = tid >> 5, lane = tid & 31;
    const int t = blockIdx.x * 8 + w;
    const float4* xr = (const float4*)(x + (size_t)t * D_DIM);
    float4 xv[8];
#pragma unroll
    for (int i = 0; i < 8; i++) xv[i] = xr[lane + i * 32];

    float acc[8];
#pragma unroll
    for (int e = 0; e < 8; e++) {
        float a = 0.0f;
#pragma unroll
        for (int i = 0; i < 8; i++) {
            const float4 gv = *(const float4*)&gwT[e][(lane + i * 32) * 4];
            a += xv[i].x * gv.x + xv[i].y * gv.y + xv[i].z * gv.z + xv[i].w * gv.w;
        }
        acc[e] = a;
    }
#pragma unroll
    for (int s = 16; s > 0; s >>= 1) {
#pragma unroll
        for (int e = 0; e < 8; e++)
            acc[e] += __shfl_xor_sync(0xffffffffu, acc[e], s);
    }
    if (lane == 0) {
        int i0 = 0;
#pragma unroll
        for (int e = 1; e < 8; e++) if (acc[e] > acc[i0]) i0 = e;
        int i1 = (i0 == 0) ? 1 : 0;
#pragma unroll
        for (int e = 0; e < 8; e++) if (e != i1 && e != i0 && acc[e] > acc[i1]) i1 = e;
        float e1 = expf(acc[i1] - acc[i0]);
        float inv = 1.0f / (1.0f + e1);
        int p0 = atomicAdd(&g_counts[i0], 1);
        int p1 = atomicAdd(&g_counts[i1], 1);
        g_expidx[2 * t + 0] = i0;
        g_expidx[2 * t + 1] = i1;
        g_pos[2 * t + 0] = p0;
        g_pos[2 * t + 1] = p1;
        g_wt[2 * t + 0] = inv;
        g_wt[2 * t + 1] = e1 * inv;
    }
}

__global__ void scan_kernel() {
    if (threadIdx.x == 0) {
        int s = 0;
#pragma unroll
        for (int e = 0; e < E_NUM; e++) {
            g_offsets[e] = s;
            s += (g_counts[e] + 127) & ~127;   // pad each expert to 128
        }
        g_offsets[E_NUM] = s;
    }
}

__global__ void scatter_kernel() {
    int i = blockIdx.x * 256 + threadIdx.x;
    if (i >= A_TOT) return;
    int e = g_expidx[i];
    int s = g_offsets[e] + g_pos[i];
    g_slot[i] = s;
    g_sorted_tok[s] = i >> 1;
    g_sorted_wt[s] = g_wt[i];
}

// Fill padding slots with tok=0, wt=0.
__global__ void pad_fill_kernel() {
    int s = blockIdx.x * 256 + threadIdx.x;
    if (s >= A_PAD) return;
    int e = 0;
#pragma unroll
    for (int i = 1; i < E_NUM; i++) if (s >= g_offsets[i]) e = i;
    int local = s - g_offsets[e];
    if (local >= g_counts[e]) {
        g_sorted_tok[s] = 0;
        g_sorted_wt[s] = 0.0f;
    }
}

// ---------------- fragment pre-format kernels (fp16) ------------------------
// Gather routed x rows into A-fragment slabs.
__global__ __launch_bounds__(256) void xfrag_kernel(const float* __restrict__ x) {
    const int ch = blockIdx.x;
    const int mt = blockIdx.y;
    __shared__ float sx[128 * 20];
    __shared__ int toks[128];
    const int tid = threadIdx.x;
    if (tid < 128) toks[tid] = g_sorted_tok[mt * 128 + tid];
    __syncthreads();
#pragma unroll
    for (int p = 0; p < 2; p++) {
        int q = tid + p * 256;
        int row = q >> 2, kq = q & 3;
        float4 v = *(const float4*)(x + (size_t)toks[row] * D_DIM + ch * 16 + kq * 4);
        *(float4*)&sx[row * 20 + kq * 4] = v;
    }
    __syncthreads();
    const int mb = tid >> 5, lane = tid & 31;
    const int g = lane >> 2, t = lane & 3;
    const int r0 = mb * 16 + g;
    uint4 v;
    v.x = h2u(__floats2half2_rn(sx[r0 * 20 + 2 * t],           sx[r0 * 20 + 2 * t + 1]));
    v.y = h2u(__floats2half2_rn(sx[(r0 + 8) * 20 + 2 * t],     sx[(r0 + 8) * 20 + 2 * t + 1]));
    v.z = h2u(__floats2half2_rn(sx[r0 * 20 + 2 * t + 8],       sx[r0 * 20 + 2 * t + 9]));
    v.w = h2u(__floats2half2_rn(sx[(r0 + 8) * 20 + 2 * t + 8], sx[(r0 + 8) * 20 + 2 * t + 9]));
    uint4* dst = (uint4*)(g_xa + ((size_t)mt * NCH1 + ch) * 2048);
    dst[tid] = v;
}

// Reformat weights [e][K][N] row-major -> fp16 B-fragment slabs.
__global__ __launch_bounds__(256) void wfrag_kernel(const float* __restrict__ w,
                                                    __half* __restrict__ dstbase,
                                                    int Ndim) {
    const int nt = blockIdx.x;
    const int ch = blockIdx.y;
    const int e = blockIdx.z;
    const int Kdim = gridDim.y * 16;
    __shared__ float s[16 * 132];
    const float* src = w + (size_t)e * Kdim * Ndim + (size_t)(ch * 16) * Ndim + nt * 128;
    const int tid = threadIdx.x;
#pragma unroll
    for (int p = 0; p < 2; p++) {
        int q = tid + p * 256;
        int kk = q >> 5, nn = q & 31;
        float4 v = *(const float4*)(src + (size_t)kk * Ndim + nn * 4);
        *(float4*)&s[kk * 132 + nn * 4] = v;
    }
    __syncthreads();
    const int np = tid >> 5, lane = tid & 31;
    const int g = lane >> 2, t = lane & 3;
    const int c0 = np * 16 + g, c1 = c0 + 8;
    uint4 v;
    v.x = h2u(__floats2half2_rn(s[(2 * t) * 132 + c0],     s[(2 * t + 1) * 132 + c0]));
    v.y = h2u(__floats2half2_rn(s[(2 * t + 8) * 132 + c0], s[(2 * t + 9) * 132 + c0]));
    v.z = h2u(__floats2half2_rn(s[(2 * t) * 132 + c1],     s[(2 * t + 1) * 132 + c1]));
    v.w = h2u(__floats2half2_rn(s[(2 * t + 8) * 132 + c1], s[(2 * t + 9) * 132 + c1]));
    uint4* dst = (uint4*)(dstbase + (((size_t)e * gridDim.x + nt) * gridDim.y + ch) * 2048);
    dst[tid] = v;
}

// ---------------- mma.sync fp16 grouped GEMM (smem-free, sw-pipelined) ------
// CTA 128x128, 8 warps 4(M)x2(N), warp tile 32x64, 2 CTA/SM = 16 warps/SM.
// Operands read DIRECTLY from global fp16 fragment slabs (lane-contig LDG.128).
// Register double-buffer: chunk ch+1's 6 fragments prefetched before chunk
// ch's 16 mmas issue.
template<int NCHUNK, int FFN1>
__global__ __launch_bounds__(256, 2)
void ffn_mma(const __half* __restrict__ Afrag,
             const __half* __restrict__ Bfrag,
             const float* __restrict__ bias,
             __half* __restrict__ outh,
             int out_n) {
    const int e = blockIdx.z;
    const int cnt = g_counts[e];
    const int m0 = blockIdx.y * 128;
    if (m0 >= cnt) return;
    const int off = g_offsets[e];              // padded, multiple of 128
    const int mt = (off >> 7) + blockIdx.y;    // global M-tile index
    const int nt = blockIdx.x;

    const int tid = threadIdx.x;
    const int wid = tid >> 5;
    const int lane = tid & 31;
    const int warp_m = wid >> 1;   // 0..3
    const int warp_n = wid & 1;    // 0..1

    const uint4* au = (const uint4*)Afrag + (size_t)mt * NCHUNK * 256
                    + warp_m * 64 + lane;      // 2 A-blocks per warp_m
    const uint4* bu = (const uint4*)Bfrag + ((size_t)e * gridDim.x + nt) * NCHUNK * 256
                    + warp_n * 128 + lane;     // 4 B-blocks per warp_n

    float c[2][8][4];
#pragma unroll
    for (int mi = 0; mi < 2; mi++)
#pragma unroll
        for (int ni = 0; ni < 8; ni++)
#pragma unroll
            for (int j = 0; j < 4; j++) c[mi][ni][j] = 0.0f;

    uint4 av[2][2];
    uint4 bv[2][4];
    av[0][0] = au[0];  av[0][1] = au[32];
    bv[0][0] = bu[0];  bv[0][1] = bu[32];
    bv[0][2] = bu[64]; bv[0][3] = bu[96];

#pragma unroll 2
    for (int ch = 0; ch < NCHUNK; ch++) {
        const int cur = ch & 1;
        const int nxt = cur ^ 1;
        if (ch + 1 < NCHUNK) {
            const uint4* ap = au + (size_t)(ch + 1) * 256;
            const uint4* bp = bu + (size_t)(ch + 1) * 256;
            av[nxt][0] = ap[0];  av[nxt][1] = ap[32];
            bv[nxt][0] = bp[0];  bv[nxt][1] = bp[32];
            bv[nxt][2] = bp[64]; bv[nxt][3] = bp[96];
        }
#pragma unroll
        for (int pi = 0; pi < 4; pi++)
#pragma unroll
            for (int mi = 0; mi < 2; mi++) {
                mma_f16(c[mi][2 * pi + 0], (const uint32_t*)&av[cur][mi],
                        bv[cur][pi].x, bv[cur][pi].y);
                mma_f16(c[mi][2 * pi + 1], (const uint32_t*)&av[cur][mi],
                        bv[cur][pi].z, bv[cur][pi].w);
            }
    }

    const int g = lane >> 2;
    const int t = lane & 3;

    if (FFN1) {
        // Write h (fp16) into GEMM2 A-fragment layout, one STG.128 per
        // (mi, ni-pair). No row checks: overflow lands in 128-padding.
        const int nb = (nt * 128 + warp_n * 64) >> 4;   // base ch2
        const float* bcol = bias + (size_t)e * F_DIM + nt * 128 + warp_n * 64 + t * 2;
#pragma unroll
        for (int mi = 0; mi < 2; mi++) {
            const int mb = warp_m * 2 + mi;
#pragma unroll
            for (int p = 0; p < 4; p++) {
                float2 b0 = *(const float2*)(bcol + p * 16);
                float2 b1 = *(const float2*)(bcol + p * 16 + 8);
                const int ni0 = 2 * p, ni1 = 2 * p + 1;
                uint4 u;
                u.x = h2u(__floats2half2_rn(gelu_exact(c[mi][ni0][0] + b0.x),
                                            gelu_exact(c[mi][ni0][1] + b0.y)));
                u.y = h2u(__floats2half2_rn(gelu_exact(c[mi][ni0][2] + b0.x),
                                            gelu_exact(c[mi][ni0][3] + b0.y)));
                u.z = h2u(__floats2half2_rn(gelu_exact(c[mi][ni1][0] + b1.x),
                                            gelu_exact(c[mi][ni1][1] + b1.y)));
                u.w = h2u(__floats2half2_rn(gelu_exact(c[mi][ni1][2] + b1.x),
                                            gelu_exact(c[mi][ni1][3] + b1.y)));
                *(uint4*)(outh + (((size_t)mt * NCH2 + nb + p) * 8 + mb) * 256
                          + lane * 8) = u;
            }
        }
    } else {
        // Write y = wt*(acc + b2) as fp16 row-major to g_y.
        const float* brow = bias + (size_t)e * out_n + nt * 128;
#pragma unroll
        for (int mi = 0; mi < 2; mi++) {
#pragma unroll
            for (int rh = 0; rh < 2; rh++) {
                int r = warp_m * 32 + mi * 16 + g + rh * 8;
                size_t srow = (size_t)(off + m0 + r);   // pad rows: wt=0, never read
                float wt = g_sorted_wt[srow];
                __half* orow = outh + srow * (size_t)out_n + nt * 128;
#pragma unroll
                for (int ni = 0; ni < 8; ni++) {
                    int col = warp_n * 64 + ni * 8 + t * 2;
                    float2 bb = *(const float2*)(brow + col);
                    __half2 o = __floats2half2_rn(
                        wt * (c[mi][ni][rh * 2 + 0] + bb.x),
                        wt * (c[mi][ni][rh * 2 + 1] + bb.y));
                    *(__half2*)(orow + col) = o;
                }
            }
        }
    }
}

// out[t, d] = y[slot0(t), d] + y[slot1(t), d]  (fp16 y, fp32 out, float4-wide)
__global__ __launch_bounds__(256) void combine_kernel(float4* __restrict__ out) {
    int i4 = blockIdx.x * 256 + threadIdx.x;   // float4 index, T*D/4 total
    int t = i4 >> 8;
    int d4 = i4 & 255;
    int s0 = g_slot[2 * t + 0];
    int s1 = g_slot[2 * t + 1];
    const __half2* ya = (const __half2*)(g_y + (size_t)s0 * D_DIM + d4 * 4);
    const __half2* yb = (const __half2*)(g_y + (size_t)s1 * D_DIM + d4 * 4);
    __half2 a0 = ya[0], a1 = ya[1];
    __half2 b0 = yb[0], b1 = yb[1];
    float2 fa0 = __half22float2(a0), fa1 = __half22float2(a1);
    float2 fb0 = __half22float2(b0), fb1 = __half22float2(b1);
    float4 o;
    o.x = fa0.x + fb0.x;
    o.y = fa0.y + fb0.y;
    o.z = fa1.x + fb1.x;
    o.w = fa1.y + fb1.y;
    out[i4] = o;
}

// ---------------------------------------------------------------------------
extern "C" void kernel_launch(void* const* d_in, const int* in_sizes, int n_in,
                              void* d_out, int out_size) {
    const float* x  = (const float*)d_in[0];
    const float* gw = (const float*)d_in[1];
    const float* w1 = (const float*)d_in[2];
    const float* b1 = (const float*)d_in[3];
    const float* w2 = (const float*)d_in[4];
    const float* b2 = (const float*)d_in[5];
    float* out = (float*)d_out;

    __half* xa;  cudaGetSymbolAddress((void**)&xa,  g_xa);
    __half* hf;  cudaGetSymbolAddress((void**)&hf,  g_hf);
    __half* w1f; cudaGetSymbolAddress((void**)&w1f, g_w1f);
    __half* w2f; cudaGetSymbolAddress((void**)&w2f, g_w2f);
    __half* ybuf; cudaGetSymbolAddress((void**)&ybuf, g_y);

    zero_kernel<<<1, 32>>>();
    gate_kernel<<<T_TOK / 8, 256>>>(x, gw);
    scan_kernel<<<1, 32>>>();
    scatter_kernel<<<A_TOT / 256, 256>>>();
    pad_fill_kernel<<<(A_PAD + 255) / 256, 256>>>();

    // Pre-format: weights + gathered activations into fp16 fragment slabs.
    wfrag_kernel<<<dim3(NT1, NCH1, E_NUM), 256>>>(w1, w1f, F_DIM);
    wfrag_kernel<<<dim3(NT2, NCH2, E_NUM), 256>>>(w2, w2f, D_DIM);
    xfrag_kernel<<<dim3(NCH1, NMT), 256>>>(x);

    // GEMM1: h = gelu(x @ w1 + b1) -> g_hf (fp16 fragment layout)
    ffn_mma<NCH1, 1><<<dim3(NT1, A_TOT / 128, E_NUM), 256>>>(
        xa, w1f, b1, hf, F_DIM);
    // GEMM2: y = wt * (h @ w2 + b2) -> g_y (fp16 row-major)
    ffn_mma<NCH2, 0><<<dim3(NT2, A_TOT / 128, E_NUM), 256>>>(
        hf, w2f, b2, ybuf, D_DIM);

    combine_kernel<<<(T_TOK * D_DIM / 4) / 256, 256>>>((float4*)out);
}